// round 2
// baseline (speedup 1.0000x reference)
#include <cuda_runtime.h>
#include <math.h>

// Problem constants (fixed by dataset)
#define D_MODEL  2048
#define N_HEADS  16
#define HEAD_DIM 128
#define BATCH    2
#define SEQ      2048
#define NTOK     (BATCH * SEQ)

// Scratch (device globals; no allocations allowed)
__device__ float g_q [NTOK * D_MODEL];   // Q projection (token, d) head h at cols h*128..
__device__ float g_k [NTOK * HEAD_DIM];  // shared K head
__device__ float g_v [NTOK * HEAD_DIM];  // shared V head
__device__ float g_ao[NTOK * D_MODEL];   // attention output before Wo

// ---------------------------------------------------------------------------
// SGEMM: C(MxN) = A(MxK) @ B(KxN) + bias(N).  BM=BN=128, BK=8, 8x8/thread.
// ---------------------------------------------------------------------------
__global__ __launch_bounds__(256) void sgemm_bias_kernel(
    int M, int N, int K,
    const float* __restrict__ A,
    const float* __restrict__ B,
    const float* __restrict__ bias,
    float* __restrict__ C)
{
    const int BM = 128, BN = 128, BK = 8, TM = 8, TN = 8;
    __shared__ float As[BK][BM];
    __shared__ float Bs[BK][BN];

    const int tid = threadIdx.x;                // 256 threads
    const int threadCol = tid % (BN / TN);      // 0..15
    const int threadRow = tid / (BN / TN);      // 0..15
    const int innerRowA = tid / (BK / 4);       // 0..127
    const int innerColA = tid % (BK / 4);       // 0..1
    const int innerRowB = tid / (BN / 4);       // 0..7
    const int innerColB = tid % (BN / 4);       // 0..31

    const float* Ab = A + (size_t)blockIdx.y * BM * K;
    const float* Bb = B + (size_t)blockIdx.x * BN;

    float acc[TM][TN];
#pragma unroll
    for (int i = 0; i < TM; i++)
#pragma unroll
        for (int j = 0; j < TN; j++) acc[i][j] = 0.0f;

    for (int k0 = 0; k0 < K; k0 += BK) {
        // Load A tile (transposed into As) and B tile
        float4 a = *(const float4*)&Ab[(size_t)innerRowA * K + k0 + innerColA * 4];
        As[innerColA * 4 + 0][innerRowA] = a.x;
        As[innerColA * 4 + 1][innerRowA] = a.y;
        As[innerColA * 4 + 2][innerRowA] = a.z;
        As[innerColA * 4 + 3][innerRowA] = a.w;
        *(float4*)&Bs[innerRowB][innerColB * 4] =
            *(const float4*)&Bb[(size_t)(k0 + innerRowB) * N + innerColB * 4];
        __syncthreads();

#pragma unroll
        for (int kk = 0; kk < BK; kk++) {
            float regM[TM], regN[TN];
#pragma unroll
            for (int i = 0; i < TM; i++) regM[i] = As[kk][threadRow * TM + i];
#pragma unroll
            for (int j = 0; j < TN; j++) regN[j] = Bs[kk][threadCol * TN + j];
#pragma unroll
            for (int i = 0; i < TM; i++)
#pragma unroll
                for (int j = 0; j < TN; j++)
                    acc[i][j] += regM[i] * regN[j];
        }
        __syncthreads();
    }

    const int rowBase = blockIdx.y * BM + threadRow * TM;
    const int colBase = blockIdx.x * BN + threadCol * TN;
#pragma unroll
    for (int i = 0; i < TM; i++) {
#pragma unroll
        for (int j = 0; j < TN; j += 4) {
            float4 t;
            t.x = acc[i][j + 0] + bias[colBase + j + 0];
            t.y = acc[i][j + 1] + bias[colBase + j + 1];
            t.z = acc[i][j + 2] + bias[colBase + j + 2];
            t.w = acc[i][j + 3] + bias[colBase + j + 3];
            *(float4*)&C[(size_t)(rowBase + i) * N + colBase + j] = t;
        }
    }
}

// ---------------------------------------------------------------------------
// Flash-attention MQA: per (b, h, 64-query tile), online softmax over 2048 keys.
// 256 threads: 16x16 grid, each thread owns 4 score rows x 4 score cols,
// and 4 rows x 8 cols of the O accumulator.
// Mask arrives as int32 (bool -> int32 in the harness).
// ---------------------------------------------------------------------------
#define BQ   64
#define BKT  64
#define HDP  132   // padded head_dim stride (float4-aligned, conflict-reducing)
#define SP   68    // padded score-tile stride

__global__ __launch_bounds__(256) void mqa_attn_kernel(
    const float* __restrict__ Q,
    const float* __restrict__ Kg,
    const float* __restrict__ Vg,
    const int* __restrict__ mask,
    float* __restrict__ Og)
{
    extern __shared__ float sm[];
    float* Qs = sm;                    // BQ  x HDP
    float* Ks = Qs + BQ * HDP;         // BKT x HDP
    float* Vs = Ks + BKT * HDP;        // BKT x HDP
    float* Ss = Vs + BKT * HDP;        // BQ  x SP
    int*   ms = (int*)(Ss + BQ * SP);  // BKT ints

    const int tid = threadIdx.x;
    const int tx = tid & 15;           // score-col group
    const int ty = tid >> 4;           // score-row group
    const int qt = blockIdx.x, h = blockIdx.y, b = blockIdx.z;
    const int q0 = qt * BQ;

    // Load Q tile (64 x 128)
    const float* Qp = Q + ((size_t)(b * SEQ + q0)) * D_MODEL + h * HEAD_DIM;
    for (int i = tid; i < BQ * HEAD_DIM / 4; i += 256) {
        int r = i >> 5;               // HEAD_DIM/4 == 32
        int c = (i & 31) << 2;
        *(float4*)&Qs[r * HDP + c] = *(const float4*)&Qp[(size_t)r * D_MODEL + c];
    }

    float m_i[4], l_i[4], Oacc[4][8];
#pragma unroll
    for (int i = 0; i < 4; i++) {
        m_i[i] = -1e30f; l_i[i] = 0.0f;
#pragma unroll
        for (int c = 0; c < 8; c++) Oacc[i][c] = 0.0f;
    }

    const float scale = 0.08838834764831845f;   // 1/sqrt(128)

    for (int k0 = 0; k0 < SEQ; k0 += BKT) {
        __syncthreads();   // protect Ks/Vs/Ss reuse from previous iteration
        const float* Kp = Kg + ((size_t)(b * SEQ + k0)) * HEAD_DIM;
        const float* Vp = Vg + ((size_t)(b * SEQ + k0)) * HEAD_DIM;
        for (int i = tid; i < BKT * HEAD_DIM / 4; i += 256) {
            int r = i >> 5;
            int c = (i & 31) << 2;
            *(float4*)&Ks[r * HDP + c] = *(const float4*)&Kp[(size_t)r * HEAD_DIM + c];
            *(float4*)&Vs[r * HDP + c] = *(const float4*)&Vp[(size_t)r * HEAD_DIM + c];
        }
        if (tid < BKT) ms[tid] = mask[(size_t)b * SEQ + k0 + tid];
        __syncthreads();

        // ---- Scores: 4x4 per thread, S = Qs @ Ks^T ----
        float acc[4][4];
#pragma unroll
        for (int i = 0; i < 4; i++)
#pragma unroll
            for (int j = 0; j < 4; j++) acc[i][j] = 0.0f;

#pragma unroll 4
        for (int kk = 0; kk < HEAD_DIM; kk += 4) {
            float4 qv[4], kv[4];
#pragma unroll
            for (int i = 0; i < 4; i++) qv[i] = *(float4*)&Qs[(ty * 4 + i) * HDP + kk];
#pragma unroll
            for (int j = 0; j < 4; j++) kv[j] = *(float4*)&Ks[(tx * 4 + j) * HDP + kk];
#pragma unroll
            for (int i = 0; i < 4; i++)
#pragma unroll
                for (int j = 0; j < 4; j++)
                    acc[i][j] += qv[i].x * kv[j].x + qv[i].y * kv[j].y
                               + qv[i].z * kv[j].z + qv[i].w * kv[j].w;
        }

        // mask + scale
        float s[4][4];
#pragma unroll
        for (int j = 0; j < 4; j++) {
            bool mk = (ms[tx * 4 + j] != 0);
#pragma unroll
            for (int i = 0; i < 4; i++)
                s[i][j] = mk ? acc[i][j] * scale : -1e9f;
        }

        // ---- Online softmax per row (16 threads per score row, xor-shuffle) ----
#pragma unroll
        for (int i = 0; i < 4; i++) {
            float rmax = fmaxf(fmaxf(s[i][0], s[i][1]), fmaxf(s[i][2], s[i][3]));
#pragma unroll
            for (int off = 8; off > 0; off >>= 1)
                rmax = fmaxf(rmax, __shfl_xor_sync(0xffffffffu, rmax, off));
            float mnew = fmaxf(m_i[i], rmax);
            float p[4], rsum = 0.0f;
#pragma unroll
            for (int j = 0; j < 4; j++) { p[j] = __expf(s[i][j] - mnew); rsum += p[j]; }
#pragma unroll
            for (int off = 8; off > 0; off >>= 1)
                rsum += __shfl_xor_sync(0xffffffffu, rsum, off);
            float corr = __expf(m_i[i] - mnew);
            l_i[i] = l_i[i] * corr + rsum;
            m_i[i] = mnew;
#pragma unroll
            for (int c = 0; c < 8; c++) Oacc[i][c] *= corr;
#pragma unroll
            for (int j = 0; j < 4; j++)
                Ss[(ty * 4 + i) * SP + tx * 4 + j] = p[j];
        }
        __syncthreads();

        // ---- O += P @ V  (thread: rows ty*4+i, cols tx*8..tx*8+7) ----
#pragma unroll 4
        for (int kk = 0; kk < BKT; kk++) {
            float pr[4];
#pragma unroll
            for (int i = 0; i < 4; i++) pr[i] = Ss[(ty * 4 + i) * SP + kk];
            float4 v0 = *(float4*)&Vs[kk * HDP + tx * 8];
            float4 v1 = *(float4*)&Vs[kk * HDP + tx * 8 + 4];
#pragma unroll
            for (int i = 0; i < 4; i++) {
                Oacc[i][0] += pr[i] * v0.x;
                Oacc[i][1] += pr[i] * v0.y;
                Oacc[i][2] += pr[i] * v0.z;
                Oacc[i][3] += pr[i] * v0.w;
                Oacc[i][4] += pr[i] * v1.x;
                Oacc[i][5] += pr[i] * v1.y;
                Oacc[i][6] += pr[i] * v1.z;
                Oacc[i][7] += pr[i] * v1.w;
            }
        }
    }

    // Epilogue: O /= l, write to (token, h*128 + c)
    float* Op = Og + ((size_t)(b * SEQ + q0)) * D_MODEL + h * HEAD_DIM;
#pragma unroll
    for (int i = 0; i < 4; i++) {
        int r = ty * 4 + i;
        float inv = 1.0f / l_i[i];
        float4 o0, o1;
        o0.x = Oacc[i][0] * inv; o0.y = Oacc[i][1] * inv;
        o0.z = Oacc[i][2] * inv; o0.w = Oacc[i][3] * inv;
        o1.x = Oacc[i][4] * inv; o1.y = Oacc[i][5] * inv;
        o1.z = Oacc[i][6] * inv; o1.w = Oacc[i][7] * inv;
        *(float4*)&Op[(size_t)r * D_MODEL + tx * 8]     = o0;
        *(float4*)&Op[(size_t)r * D_MODEL + tx * 8 + 4] = o1;
    }
}

// ---------------------------------------------------------------------------
extern "C" void kernel_launch(void* const* d_in, const int* in_sizes, int n_in,
                              void* d_out, int out_size)
{
    const float* x    = (const float*)d_in[0];
    const int*   mask = (const int*)d_in[1];     // bool -> int32 in harness
    const float* Wq   = (const float*)d_in[2];
    const float* bq   = (const float*)d_in[3];
    const float* Wk   = (const float*)d_in[4];
    const float* bk   = (const float*)d_in[5];
    const float* Wv   = (const float*)d_in[6];
    const float* bv   = (const float*)d_in[7];
    const float* Wo   = (const float*)d_in[8];
    const float* bo   = (const float*)d_in[9];
    float* out = (float*)d_out;

    float *q, *k, *v, *ao;
    cudaGetSymbolAddress((void**)&q,  g_q);
    cudaGetSymbolAddress((void**)&k,  g_k);
    cudaGetSymbolAddress((void**)&v,  g_v);
    cudaGetSymbolAddress((void**)&ao, g_ao);

    dim3 blk(256);

    // Projections
    sgemm_bias_kernel<<<dim3(D_MODEL / 128, NTOK / 128), blk>>>(
        NTOK, D_MODEL, D_MODEL, x, Wq, bq, q);
    sgemm_bias_kernel<<<dim3(1, NTOK / 128), blk>>>(
        NTOK, HEAD_DIM, D_MODEL, x, Wk, bk, k);
    sgemm_bias_kernel<<<dim3(1, NTOK / 128), blk>>>(
        NTOK, HEAD_DIM, D_MODEL, x, Wv, bv, v);

    // Attention
    size_t smem = (size_t)(BQ * HDP + 2 * BKT * HDP + BQ * SP) * sizeof(float)
                + BKT * sizeof(int);
    cudaFuncSetAttribute(mqa_attn_kernel,
                         cudaFuncAttributeMaxDynamicSharedMemorySize, (int)smem);
    mqa_attn_kernel<<<dim3(SEQ / BQ, N_HEADS, BATCH), blk, smem>>>(q, k, v, mask, ao);

    // Output projection
    sgemm_bias_kernel<<<dim3(D_MODEL / 128, NTOK / 128), blk>>>(
        NTOK, D_MODEL, D_MODEL, ao, Wo, bo, out);
}

// round 3
// speedup vs baseline: 4.4264x; 4.4264x over previous
#include <cuda_runtime.h>
#include <cstdint>
#include <math.h>

#define D_MODEL  2048
#define N_HEADS  16
#define HEAD_DIM 128
#define BATCH    2
#define SEQ      2048
#define NTOK     (BATCH * SEQ)

__device__ float g_q [NTOK * D_MODEL];
__device__ float g_k [NTOK * HEAD_DIM];
__device__ float g_v [NTOK * HEAD_DIM];
__device__ float g_ao[NTOK * D_MODEL];

// ---------------------------------------------------------------------------
// TF32 helpers
// ---------------------------------------------------------------------------
__device__ __forceinline__ uint32_t f2tf32(float x) {
    uint32_t r;
    asm("cvt.rna.tf32.f32 %0, %1;" : "=r"(r) : "f"(x));
    return r;
}

__device__ __forceinline__ void mma_tf32(float* d,
    uint32_t a0, uint32_t a1, uint32_t a2, uint32_t a3,
    uint32_t b0, uint32_t b1)
{
    asm volatile(
        "mma.sync.aligned.m16n8k8.row.col.f32.tf32.tf32.f32 "
        "{%0,%1,%2,%3},{%4,%5,%6,%7},{%8,%9},{%0,%1,%2,%3};"
        : "+f"(d[0]), "+f"(d[1]), "+f"(d[2]), "+f"(d[3])
        : "r"(a0), "r"(a1), "r"(a2), "r"(a3), "r"(b0), "r"(b1));
}

// ---------------------------------------------------------------------------
// TF32 GEMM: C(MxN) = A(MxK) @ B(KxN) + bias. BM=BN=128, BK=32, 8 warps @64x32.
// A smem m-major pad 36 (conflict-free A-frag loads), B smem k-major pad 136.
// ---------------------------------------------------------------------------
#define GBM 128
#define GBN 128
#define GBK 32
#define ASTR 36
#define BSTR 136

__global__ __launch_bounds__(256) void tf32_gemm_bias(
    int M, int N, int K,
    const float* __restrict__ A,
    const float* __restrict__ B,
    const float* __restrict__ bias,
    float* __restrict__ C)
{
    __shared__ uint32_t As[GBM * ASTR];
    __shared__ uint32_t Bs[GBK * BSTR];

    const int tid  = threadIdx.x;
    const int wid  = tid >> 5;
    const int lane = tid & 31;
    const int g    = lane >> 2;
    const int t4   = lane & 3;
    const int wm   = (wid >> 2) * 64;   // 0 or 64
    const int wn   = (wid & 3) * 32;    // 0,32,64,96

    const float* Ab = A + (size_t)blockIdx.y * GBM * K;
    const float* Bb = B + (size_t)blockIdx.x * GBN;

    float acc[4][4][4];
#pragma unroll
    for (int mi = 0; mi < 4; mi++)
#pragma unroll
        for (int ni = 0; ni < 4; ni++)
#pragma unroll
            for (int r = 0; r < 4; r++) acc[mi][ni][r] = 0.0f;

    const int arow0 = tid >> 3;        // 0..31
    const int acol  = (tid & 7) * 4;   // 0..28
    const int brow0 = tid >> 5;        // 0..7
    const int bcol  = (tid & 31) * 4;  // 0..124

    for (int k0 = 0; k0 < K; k0 += GBK) {
        // A tile 128x32 -> As[m][k] (tf32), 4 float4 per thread
#pragma unroll
        for (int i = 0; i < 4; i++) {
            int row = arow0 + i * 32;
            float4 a = *(const float4*)&Ab[(size_t)row * K + k0 + acol];
            uint4 u = make_uint4(f2tf32(a.x), f2tf32(a.y), f2tf32(a.z), f2tf32(a.w));
            *(uint4*)&As[row * ASTR + acol] = u;
        }
        // B tile 32x128 -> Bs[k][n] (tf32), 4 float4 per thread
#pragma unroll
        for (int i = 0; i < 4; i++) {
            int row = brow0 + i * 8;
            float4 b = *(const float4*)&Bb[(size_t)(k0 + row) * N + bcol];
            uint4 u = make_uint4(f2tf32(b.x), f2tf32(b.y), f2tf32(b.z), f2tf32(b.w));
            *(uint4*)&Bs[row * BSTR + bcol] = u;
        }
        __syncthreads();

#pragma unroll
        for (int ks = 0; ks < 4; ks++) {
            const int kk = ks * 8;
            uint32_t a[4][4];
#pragma unroll
            for (int mi = 0; mi < 4; mi++) {
                const int r0 = wm + mi * 16 + g;
                a[mi][0] = As[(r0    ) * ASTR + kk + t4];
                a[mi][1] = As[(r0 + 8) * ASTR + kk + t4];
                a[mi][2] = As[(r0    ) * ASTR + kk + t4 + 4];
                a[mi][3] = As[(r0 + 8) * ASTR + kk + t4 + 4];
            }
#pragma unroll
            for (int ni = 0; ni < 4; ni++) {
                const int c0 = wn + ni * 8 + g;
                uint32_t b0 = Bs[(kk + t4    ) * BSTR + c0];
                uint32_t b1 = Bs[(kk + t4 + 4) * BSTR + c0];
#pragma unroll
                for (int mi = 0; mi < 4; mi++)
                    mma_tf32(acc[mi][ni], a[mi][0], a[mi][1], a[mi][2], a[mi][3], b0, b1);
            }
        }
        __syncthreads();
    }

    const int rowBase = blockIdx.y * GBM + wm;
    const int colBase = blockIdx.x * GBN + wn;
#pragma unroll
    for (int mi = 0; mi < 4; mi++) {
#pragma unroll
        for (int ni = 0; ni < 4; ni++) {
            const int col = colBase + ni * 8 + 2 * t4;
            const int r0  = rowBase + mi * 16 + g;
            float2 v0, v1;
            v0.x = acc[mi][ni][0] + bias[col];
            v0.y = acc[mi][ni][1] + bias[col + 1];
            v1.x = acc[mi][ni][2] + bias[col];
            v1.y = acc[mi][ni][3] + bias[col + 1];
            *(float2*)&C[(size_t)r0 * N + col]       = v0;
            *(float2*)&C[(size_t)(r0 + 8) * N + col] = v1;
        }
    }
}

// ---------------------------------------------------------------------------
// Fused K/V projection, fp32 (precision-critical V path).
// BM=64, BN=128, BK=16, 128 threads, 8x8/thread. blockIdx.x: 0->K, 1->V.
// ---------------------------------------------------------------------------
__global__ __launch_bounds__(128) void kv_proj_kernel(
    const float* __restrict__ x,
    const float* __restrict__ Wk, const float* __restrict__ bk,
    const float* __restrict__ Wv, const float* __restrict__ bv,
    float* __restrict__ Kout, float* __restrict__ Vout)
{
    const float* W    = blockIdx.x ? Wv : Wk;
    const float* bias = blockIdx.x ? bv : bk;
    float*       out  = blockIdx.x ? Vout : Kout;

    __shared__ float As[16][68];    // k-major, transposed A
    __shared__ float Bs[16][128];

    const int tid = threadIdx.x;
    const int tr  = tid / 16;       // 0..7
    const int tc  = tid % 16;       // 0..15

    float acc[8][8];
#pragma unroll
    for (int i = 0; i < 8; i++)
#pragma unroll
        for (int j = 0; j < 8; j++) acc[i][j] = 0.0f;

    const float* Ab = x + (size_t)blockIdx.y * 64 * D_MODEL;
    const int ar = tid >> 2;          // 0..31
    const int ac = (tid & 3) * 4;     // 0..12
    const int br = tid >> 5;          // 0..3
    const int bc = (tid & 31) * 4;    // 0..124

    for (int k0 = 0; k0 < D_MODEL; k0 += 16) {
#pragma unroll
        for (int rr = 0; rr < 2; rr++) {
            int row = ar + rr * 32;
            float4 a = *(const float4*)&Ab[(size_t)row * D_MODEL + k0 + ac];
            As[ac + 0][row] = a.x;
            As[ac + 1][row] = a.y;
            As[ac + 2][row] = a.z;
            As[ac + 3][row] = a.w;
        }
#pragma unroll
        for (int rr = 0; rr < 4; rr++) {
            int row = br + rr * 4;
            *(float4*)&Bs[row][bc] =
                *(const float4*)&W[(size_t)(k0 + row) * HEAD_DIM + bc];
        }
        __syncthreads();

#pragma unroll
        for (int kk = 0; kk < 16; kk++) {
            float regM[8], regN[8];
#pragma unroll
            for (int i = 0; i < 8; i++) regM[i] = As[kk][tr * 8 + i];
#pragma unroll
            for (int j = 0; j < 8; j++) regN[j] = Bs[kk][tc * 8 + j];
#pragma unroll
            for (int i = 0; i < 8; i++)
#pragma unroll
                for (int j = 0; j < 8; j++)
                    acc[i][j] += regM[i] * regN[j];
        }
        __syncthreads();
    }

    const int rowBase = blockIdx.y * 64 + tr * 8;
    const int colBase = tc * 8;
#pragma unroll
    for (int i = 0; i < 8; i++) {
#pragma unroll
        for (int j = 0; j < 8; j += 4) {
            float4 t;
            t.x = acc[i][j + 0] + bias[colBase + j + 0];
            t.y = acc[i][j + 1] + bias[colBase + j + 1];
            t.z = acc[i][j + 2] + bias[colBase + j + 2];
            t.w = acc[i][j + 3] + bias[colBase + j + 3];
            *(float4*)&out[(size_t)(rowBase + i) * HEAD_DIM + colBase + j] = t;
        }
    }
}

// ---------------------------------------------------------------------------
// TF32 MMA flash attention (MQA). BQ=128, BKT=64, 8 warps (16 rows each).
// Score and PV both via m16n8k8; P remapped C-frag -> A-frag by shuffles.
// ---------------------------------------------------------------------------
#define AQ 128
#define AK 64
#define QP 132
#define KP 132
#define VP 136

__global__ __launch_bounds__(256) void mqa_attn_tf32(
    const float* __restrict__ Q,
    const float* __restrict__ Kg,
    const float* __restrict__ Vg,
    const int* __restrict__ mask,
    float* __restrict__ Og)
{
    extern __shared__ uint32_t sm_u[];
    uint32_t* Qs   = sm_u;                 // AQ x QP
    uint32_t* Ks   = Qs + AQ * QP;         // AK x KP
    uint32_t* Vs   = Ks + AK * KP;         // AK x VP
    float*   sbias = (float*)(Vs + AK * VP);  // AK

    const int tid  = threadIdx.x;
    const int wid  = tid >> 5;
    const int lane = tid & 31;
    const int g    = lane >> 2;
    const int t4   = lane & 3;
    const int b  = blockIdx.z, h = blockIdx.y;
    const int q0 = blockIdx.x * AQ;
    const int wrow = wid * 16;

    // Load Q tile (tf32)
    const float* Qp = Q + ((size_t)(b * SEQ + q0)) * D_MODEL + h * HEAD_DIM;
    for (int i = tid; i < AQ * HEAD_DIM / 4; i += 256) {
        int r = i >> 5, c = (i & 31) << 2;
        float4 qv = *(const float4*)&Qp[(size_t)r * D_MODEL + c];
        Qs[r * QP + c + 0] = f2tf32(qv.x);
        Qs[r * QP + c + 1] = f2tf32(qv.y);
        Qs[r * QP + c + 2] = f2tf32(qv.z);
        Qs[r * QP + c + 3] = f2tf32(qv.w);
    }

    float m0 = -1e30f, m1 = -1e30f, l0 = 0.0f, l1 = 0.0f;
    float o[16][4];
#pragma unroll
    for (int n = 0; n < 16; n++)
#pragma unroll
        for (int r = 0; r < 4; r++) o[n][r] = 0.0f;

    const float scale = 0.08838834764831845f;  // 1/sqrt(128)

    for (int k0 = 0; k0 < SEQ; k0 += AK) {
        __syncthreads();
        const float* Kp = Kg + ((size_t)(b * SEQ + k0)) * HEAD_DIM;
        const float* Vp = Vg + ((size_t)(b * SEQ + k0)) * HEAD_DIM;
        for (int i = tid; i < AK * HEAD_DIM / 4; i += 256) {
            int r = i >> 5, c = (i & 31) << 2;
            float4 kv = *(const float4*)&Kp[(size_t)r * HEAD_DIM + c];
            Ks[r * KP + c + 0] = f2tf32(kv.x);
            Ks[r * KP + c + 1] = f2tf32(kv.y);
            Ks[r * KP + c + 2] = f2tf32(kv.z);
            Ks[r * KP + c + 3] = f2tf32(kv.w);
            float4 vv = *(const float4*)&Vp[(size_t)r * HEAD_DIM + c];
            Vs[r * VP + c + 0] = f2tf32(vv.x);
            Vs[r * VP + c + 1] = f2tf32(vv.y);
            Vs[r * VP + c + 2] = f2tf32(vv.z);
            Vs[r * VP + c + 3] = f2tf32(vv.w);
        }
        if (tid < AK)
            sbias[tid] = mask[(size_t)b * SEQ + k0 + tid] ? 0.0f : -1e9f;
        __syncthreads();

        // ---- Scores: S = Q @ K^T, 8 n-frags per warp ----
        float s[8][4];
#pragma unroll
        for (int j = 0; j < 8; j++)
#pragma unroll
            for (int r = 0; r < 4; r++) s[j][r] = 0.0f;

#pragma unroll
        for (int ks = 0; ks < 16; ks++) {
            const int kk = ks * 8;
            uint32_t a0 = Qs[(wrow + g    ) * QP + kk + t4];
            uint32_t a1 = Qs[(wrow + g + 8) * QP + kk + t4];
            uint32_t a2 = Qs[(wrow + g    ) * QP + kk + t4 + 4];
            uint32_t a3 = Qs[(wrow + g + 8) * QP + kk + t4 + 4];
#pragma unroll
            for (int j = 0; j < 8; j++) {
                uint32_t b0 = Ks[(j * 8 + g) * KP + kk + t4];
                uint32_t b1 = Ks[(j * 8 + g) * KP + kk + t4 + 4];
                mma_tf32(s[j], a0, a1, a2, a3, b0, b1);
            }
        }

        // ---- scale + mask bias, row max ----
        float rmax0 = -1e30f, rmax1 = -1e30f;
#pragma unroll
        for (int j = 0; j < 8; j++) {
            float2 sb = *(float2*)&sbias[j * 8 + 2 * t4];
            s[j][0] = s[j][0] * scale + sb.x;
            s[j][1] = s[j][1] * scale + sb.y;
            s[j][2] = s[j][2] * scale + sb.x;
            s[j][3] = s[j][3] * scale + sb.y;
            rmax0 = fmaxf(rmax0, fmaxf(s[j][0], s[j][1]));
            rmax1 = fmaxf(rmax1, fmaxf(s[j][2], s[j][3]));
        }
#pragma unroll
        for (int off = 1; off <= 2; off <<= 1) {
            rmax0 = fmaxf(rmax0, __shfl_xor_sync(0xffffffffu, rmax0, off));
            rmax1 = fmaxf(rmax1, __shfl_xor_sync(0xffffffffu, rmax1, off));
        }
        const float mn0 = fmaxf(m0, rmax0);
        const float mn1 = fmaxf(m1, rmax1);
        const float c0 = __expf(m0 - mn0);
        const float c1 = __expf(m1 - mn1);
        m0 = mn0; m1 = mn1;

        float rs0 = 0.0f, rs1 = 0.0f;
        uint32_t pt[8][4];
#pragma unroll
        for (int j = 0; j < 8; j++) {
            float p0 = __expf(s[j][0] - mn0);
            float p1 = __expf(s[j][1] - mn0);
            float p2 = __expf(s[j][2] - mn1);
            float p3 = __expf(s[j][3] - mn1);
            rs0 += p0 + p1;
            rs1 += p2 + p3;
            pt[j][0] = f2tf32(p0);
            pt[j][1] = f2tf32(p1);
            pt[j][2] = f2tf32(p2);
            pt[j][3] = f2tf32(p3);
        }
#pragma unroll
        for (int off = 1; off <= 2; off <<= 1) {
            rs0 += __shfl_xor_sync(0xffffffffu, rs0, off);
            rs1 += __shfl_xor_sync(0xffffffffu, rs1, off);
        }
        l0 = l0 * c0 + rs0;
        l1 = l1 * c1 + rs1;

#pragma unroll
        for (int n = 0; n < 16; n++) {
            o[n][0] *= c0; o[n][1] *= c0;
            o[n][2] *= c1; o[n][3] *= c1;
        }

        // ---- O += P @ V. A-frags assembled from pt via shuffles. ----
        const int src1 = (g << 2) + (t4 >> 1);
        const int src2 = src1 + 2;
        const bool odd = (t4 & 1);
#pragma unroll
        for (int j = 0; j < 8; j++) {
            uint32_t x00 = __shfl_sync(0xffffffffu, pt[j][0], src1);
            uint32_t x01 = __shfl_sync(0xffffffffu, pt[j][1], src1);
            uint32_t x10 = __shfl_sync(0xffffffffu, pt[j][0], src2);
            uint32_t x11 = __shfl_sync(0xffffffffu, pt[j][1], src2);
            uint32_t x20 = __shfl_sync(0xffffffffu, pt[j][2], src1);
            uint32_t x21 = __shfl_sync(0xffffffffu, pt[j][3], src1);
            uint32_t x30 = __shfl_sync(0xffffffffu, pt[j][2], src2);
            uint32_t x31 = __shfl_sync(0xffffffffu, pt[j][3], src2);
            uint32_t a0 = odd ? x01 : x00;
            uint32_t a2 = odd ? x11 : x10;
            uint32_t a1 = odd ? x21 : x20;
            uint32_t a3 = odd ? x31 : x30;
#pragma unroll
            for (int n = 0; n < 16; n++) {
                uint32_t b0 = Vs[(j * 8 + t4    ) * VP + n * 8 + g];
                uint32_t b1 = Vs[(j * 8 + t4 + 4) * VP + n * 8 + g];
                mma_tf32(o[n], a0, a1, a2, a3, b0, b1);
            }
        }
    }

    // ---- Epilogue ----
    const float inv0 = 1.0f / l0;
    const float inv1 = 1.0f / l1;
    float* Op0 = Og + ((size_t)(b * SEQ + q0 + wrow + g    )) * D_MODEL + h * HEAD_DIM;
    float* Op1 = Og + ((size_t)(b * SEQ + q0 + wrow + g + 8)) * D_MODEL + h * HEAD_DIM;
#pragma unroll
    for (int n = 0; n < 16; n++) {
        const int col = n * 8 + 2 * t4;
        float2 v0, v1;
        v0.x = o[n][0] * inv0; v0.y = o[n][1] * inv0;
        v1.x = o[n][2] * inv1; v1.y = o[n][3] * inv1;
        *(float2*)&Op0[col] = v0;
        *(float2*)&Op1[col] = v1;
    }
}

// ---------------------------------------------------------------------------
extern "C" void kernel_launch(void* const* d_in, const int* in_sizes, int n_in,
                              void* d_out, int out_size)
{
    const float* x    = (const float*)d_in[0];
    const int*   mask = (const int*)d_in[1];
    const float* Wq   = (const float*)d_in[2];
    const float* bq   = (const float*)d_in[3];
    const float* Wk   = (const float*)d_in[4];
    const float* bk   = (const float*)d_in[5];
    const float* Wv   = (const float*)d_in[6];
    const float* bv   = (const float*)d_in[7];
    const float* Wo   = (const float*)d_in[8];
    const float* bo   = (const float*)d_in[9];
    float* out = (float*)d_out;

    float *q, *k, *v, *ao;
    cudaGetSymbolAddress((void**)&q,  g_q);
    cudaGetSymbolAddress((void**)&k,  g_k);
    cudaGetSymbolAddress((void**)&v,  g_v);
    cudaGetSymbolAddress((void**)&ao, g_ao);

    // Q projection (tf32 mma)
    tf32_gemm_bias<<<dim3(D_MODEL / GBN, NTOK / GBM), 256>>>(
        NTOK, D_MODEL, D_MODEL, x, Wq, bq, q);

    // K/V projections fused (fp32)
    kv_proj_kernel<<<dim3(2, NTOK / 64), 128>>>(x, Wk, bk, Wv, bv, k, v);

    // Attention (tf32 mma flash)
    size_t smem = (size_t)(AQ * QP + AK * KP + AK * VP) * 4 + AK * sizeof(float);
    cudaFuncSetAttribute(mqa_attn_tf32,
                         cudaFuncAttributeMaxDynamicSharedMemorySize, (int)smem);
    mqa_attn_tf32<<<dim3(SEQ / AQ, N_HEADS, BATCH), 256, smem>>>(q, k, v, mask, ao);

    // Output projection (tf32 mma)
    tf32_gemm_bias<<<dim3(D_MODEL / GBN, NTOK / GBM), 256>>>(
        NTOK, D_MODEL, D_MODEL, ao, Wo, bo, out);
}